// round 13
// baseline (speedup 1.0000x reference)
#include <cuda_runtime.h>
#include <cstdint>

#define BROWS  32768
#define KROWS  8192
#define DDIM   256
#define QSCALE 26.0f
#define INV676 (1.0f / 676.0f)
#define TH     2.2f
#define CAP    32
#define CLCAP  64

// ---------------- device globals (no cudaMalloc allowed) --------------------
__device__ __align__(16) int8_t g_z8[BROWS * DDIM];    // round(-26 * z)
__device__ __align__(16) int8_t g_cb8[KROWS * DDIM];   // round( 26 * e)
__device__ __align__(16) float  g_esq[KROWS];          // 0.5*||e||^2 exact
__device__ int   g_row_idx[BROWS];
__device__ int   g_ccnt[BROWS];                        // candidate counts
__device__ int   g_cand[BROWS * CAP];
__device__ int   g_nclamp;
__device__ int   g_clampidx[CLCAP];
__device__ float g_partial[BROWS / 64];

// ---------------- asm helpers (baseline PTX only) ----------------------------
__device__ __forceinline__ uint32_t smem_u32(const void* p) {
    uint32_t a;
    asm("{ .reg .u64 t; cvta.to.shared.u64 t, %1; cvt.u32.u64 %0, t; }"
        : "=r"(a) : "l"(p));
    return a;
}
__device__ __forceinline__ void ldmx4(uint32_t r[4], uint32_t addr) {
    asm volatile("ldmatrix.sync.aligned.m8n8.x4.shared.b16 {%0,%1,%2,%3}, [%4];\n"
        : "=r"(r[0]), "=r"(r[1]), "=r"(r[2]), "=r"(r[3]) : "r"(addr));
}
// int8 MMA: m16n8k32, s32 accumulate. Fragments byte-identical to f16 m16n8k16.
__device__ __forceinline__ void imma16832(int c[4], const uint32_t a[4],
                                          uint32_t b0, uint32_t b1) {
    asm volatile(
        "mma.sync.aligned.m16n8k32.row.col.s32.s8.s8.s32 "
        "{%0,%1,%2,%3}, {%4,%5,%6,%7}, {%8,%9}, {%0,%1,%2,%3};\n"
        : "+r"(c[0]), "+r"(c[1]), "+r"(c[2]), "+r"(c[3])
        : "r"(a[0]), "r"(a[1]), "r"(a[2]), "r"(a[3]), "r"(b0), "r"(b1));
}
__device__ __forceinline__ void cp16(uint32_t dst, const void* src) {
    asm volatile("cp.async.cg.shared.global [%0], [%1], 16;\n"
        :: "r"(dst), "l"(src));
}
#define CPC()  asm volatile("cp.async.commit_group;\n" ::: "memory")
#define CPW(n) asm volatile("cp.async.wait_group %0;\n" :: "n"(n) : "memory")

// order-preserving float<->uint encoding (for atomicMin on scores)
__device__ __forceinline__ uint32_t encf(float f) {
    uint32_t u = __float_as_uint(f);
    return (u & 0x80000000u) ? ~u : (u | 0x80000000u);
}
__device__ __forceinline__ float decf(uint32_t u) {
    uint32_t v = (u & 0x80000000u) ? (u & 0x7fffffffu) : ~u;
    return __uint_as_float(v);
}

// ---------------- prep: esq + counter resets ---------------------------------
__global__ void prep_kernel(const float* __restrict__ cb) {
    int gtid = blockIdx.x * 256 + threadIdx.x;
    if (gtid < BROWS) g_ccnt[gtid] = 0;
    if (gtid == 0) g_nclamp = 0;
    int row = blockIdx.x * 8 + (threadIdx.x >> 5);
    if (row >= KROWS) return;
    int lane = threadIdx.x & 31;
    const float4* p = reinterpret_cast<const float4*>(cb + (size_t)row * DDIM);
    float s = 0.f;
#pragma unroll
    for (int i = 0; i < 2; i++) {
        float4 v = p[lane + 32 * i];
        s += v.x * v.x + v.y * v.y + v.z * v.z + v.w * v.w;
    }
#pragma unroll
    for (int o = 16; o; o >>= 1) s += __shfl_down_sync(0xffffffffu, s, o);
    if (lane == 0) g_esq[row] = 0.5f * s;
}

// ---------------- quantizers -------------------------------------------------
__global__ void quant_z(const float* __restrict__ src) {
    int i = blockIdx.x * 256 + threadIdx.x;          // float4 index
    if (i >= BROWS * DDIM / 4) return;
    float4 v = reinterpret_cast<const float4*>(src)[i];
    int q0 = __float2int_rn(-QSCALE * v.x);
    int q1 = __float2int_rn(-QSCALE * v.y);
    int q2 = __float2int_rn(-QSCALE * v.z);
    int q3 = __float2int_rn(-QSCALE * v.w);
    bool bad = (q0 > 127 || q0 < -127 || q1 > 127 || q1 < -127 ||
                q2 > 127 || q2 < -127 || q3 > 127 || q3 < -127);
    if (bad) {
        q0 = max(-127, min(127, q0)); q1 = max(-127, min(127, q1));
        q2 = max(-127, min(127, q2)); q3 = max(-127, min(127, q3));
        g_ccnt[i >> 6] = 0x40000000;   // sentinel: force exact full scan
    }
    char4 c; c.x = (char)q0; c.y = (char)q1; c.z = (char)q2; c.w = (char)q3;
    *reinterpret_cast<char4*>(g_z8 + (size_t)i * 4) = c;
}

__global__ void quant_cb(const float* __restrict__ src) {
    int i = blockIdx.x * 256 + threadIdx.x;
    if (i >= KROWS * DDIM / 4) return;
    float4 v = reinterpret_cast<const float4*>(src)[i];
    int q0 = __float2int_rn(QSCALE * v.x);
    int q1 = __float2int_rn(QSCALE * v.y);
    int q2 = __float2int_rn(QSCALE * v.z);
    int q3 = __float2int_rn(QSCALE * v.w);
    bool bad = (q0 > 127 || q0 < -127 || q1 > 127 || q1 < -127 ||
                q2 > 127 || q2 < -127 || q3 > 127 || q3 < -127);
    if (bad) {
        q0 = max(-127, min(127, q0)); q1 = max(-127, min(127, q1));
        q2 = max(-127, min(127, q2)); q3 = max(-127, min(127, q3));
        int p = atomicAdd(&g_nclamp, 1);
        if (p < CLCAP) g_clampidx[p] = i >> 6;
    }
    char4 c; c.x = (char)q0; c.y = (char)q1; c.z = (char)q2; c.w = (char)q3;
    *reinterpret_cast<char4*>(g_cb8 + (size_t)i * 4) = c;
}

// ============================================================================
// Screen: int8 IMMA (m16n8k32), 256 thr (8 warps, 2m x 4n, warp tile m32n64).
// CTA = 64 rows x all 8192 codes. B streamed as 256-code x 128-dim chunks.
// Per-row running best in SMEM (atomicMin); codes within TH of running best
// appended as candidates for exact fp32 rescoring.
// SMEM: A 16K | B ring 2x32K | esq 2x1K | rowbest 256B  = ~83K (2 CTAs/SM)
// ============================================================================
#define S_A   0u
#define S_B   16384u
#define S_E   81920u
#define S_RB  83968u
#define SCR_SMEM 84224

__global__ __launch_bounds__(256, 2) void vq_screen() {
    extern __shared__ char sm[];
    const uint32_t sb = smem_u32(sm);
    uint32_t* rowbest = reinterpret_cast<uint32_t*>(sm + S_RB);
    const int tid = threadIdx.x, lane = tid & 31, w = tid >> 5;
    const int wm = w & 1, wn = w >> 1;
    const int row0 = blockIdx.x * 64;

    if (tid < 64) rowbest[tid] = encf(3.0e38f);

    // ---- prologue: A (16KB int8), esq tile0, B chunk 0 ----
#pragma unroll
    for (int q = 0; q < 4; q++) {
        int lin = q * 256 + tid;
        int r = lin >> 4, c = lin & 15;
        cp16(sb + S_A + r * 256 + ((c * 16) ^ ((r & 7) << 4)),
             g_z8 + (size_t)(row0 + r) * DDIM + c * 16);
    }
    if (tid < 64) cp16(sb + S_E + tid * 16, g_esq + tid * 4);
#pragma unroll
    for (int q = 0; q < 8; q++) {
        int lin = q * 256 + tid;
        int r = lin >> 3, c = lin & 7;
        cp16(sb + S_B + r * 128 + ((c * 16) ^ ((r & 7) << 4)),
             g_cb8 + (size_t)r * DDIM + c * 16);
    }
    CPC();

    const uint32_t aBase = sb + S_A + (uint32_t)(wm * 32 + (lane & 15)) * 256;
    const uint32_t aK    = (uint32_t)((lane >> 4) * 16);
    const uint32_t aSw   = (uint32_t)((lane & 7) << 4);
    const uint32_t bRow  = (uint32_t)(wn * 64 + (lane & 7) + ((lane >> 4) & 1) * 8) * 128;
    const uint32_t bK    = (uint32_t)(((lane >> 3) & 1) * 16);

    int myrow[4];
#pragma unroll
    for (int mf = 0; mf < 2; mf++)
#pragma unroll
        for (int h = 0; h < 2; h++)
            myrow[mf * 2 + h] = wm * 32 + mf * 16 + (lane >> 2) + h * 8;

    int acc[2][8][4];

    for (int cs = 0; cs < 64; cs++) {
        const int it = cs >> 1, ch = cs & 1;
        if (cs + 1 < 64) {
            const int itN = (cs + 1) >> 1, chN = (cs + 1) & 1;
            const uint32_t dstB = sb + S_B + (uint32_t)((cs + 1) & 1) * 32768;
            const int8_t* srcB = g_cb8 + (size_t)(itN * 256) * DDIM + chN * 128;
#pragma unroll
            for (int q = 0; q < 8; q++) {
                int lin = q * 256 + tid;
                int r = lin >> 3, c = lin & 7;
                cp16(dstB + r * 128 + ((c * 16) ^ ((r & 7) << 4)),
                     srcB + (size_t)r * DDIM + c * 16);
            }
            if (chN == 0 && tid < 64)
                cp16(sb + S_E + (uint32_t)(itN & 1) * 1024 + tid * 16,
                     g_esq + itN * 256 + tid * 4);
            CPC();
            CPW(1);
        } else {
            CPW(0);
        }
        __syncthreads();

        const uint32_t bufB = sb + S_B + (uint32_t)(cs & 1) * 32768;
        const float* esq_t = reinterpret_cast<const float*>(sm + S_E + (it & 1) * 1024);

        if (ch == 0) {
#pragma unroll
            for (int mf = 0; mf < 2; mf++)
#pragma unroll
                for (int nf = 0; nf < 8; nf++)
#pragma unroll
                    for (int k = 0; k < 4; k++) acc[mf][nf][k] = 0;
        }

#pragma unroll
        for (int ks = 0; ks < 4; ks++) {
            uint32_t a[2][4];
#pragma unroll
            for (int mf = 0; mf < 2; mf++)
                ldmx4(a[mf], aBase + mf * 4096 +
                              (((uint32_t)(ch * 128 + ks * 32) + aK) ^ aSw));
            uint32_t b[4][4];
#pragma unroll
            for (int p = 0; p < 4; p++)
                ldmx4(b[p], bufB + bRow + p * 2048 +
                              (((uint32_t)(ks * 32) + bK) ^ aSw));
#pragma unroll
            for (int mf = 0; mf < 2; mf++)
#pragma unroll
                for (int p = 0; p < 4; p++) {
                    imma16832(acc[mf][2 * p],     a[mf], b[p][0], b[p][1]);
                    imma16832(acc[mf][2 * p + 1], a[mf], b[p][2], b[p][3]);
                }
        }

        if (ch == 1) {
            if (it == 0) {
                // tile 0: pass 1 = mins only (rowbest starts at +inf)
#pragma unroll
                for (int mf = 0; mf < 2; mf++)
#pragma unroll
                    for (int h = 0; h < 2; h++) {
                        float bl = 3.0e38f;
#pragma unroll
                        for (int nf = 0; nf < 8; nf++)
#pragma unroll
                            for (int j = 0; j < 2; j++) {
                                float s = esq_t[wn * 64 + nf * 8 + (lane & 3) * 2 + j]
                                        + (float)acc[mf][nf][h * 2 + j] * INV676;
                                bl = fminf(bl, s);
                            }
                        atomicMin(&rowbest[myrow[mf * 2 + h]], encf(bl));
                    }
                __syncthreads();
            }
            // appends (and, for it>0, min updates) using (possibly stale) rowbest
#pragma unroll
            for (int mf = 0; mf < 2; mf++)
#pragma unroll
                for (int h = 0; h < 2; h++) {
                    const int ls = mf * 2 + h;
                    const float thr = decf(rowbest[myrow[ls]]) + TH;
                    float bl = 3.0e38f;
#pragma unroll
                    for (int nf = 0; nf < 8; nf++)
#pragma unroll
                        for (int j = 0; j < 2; j++) {
                            float s = esq_t[wn * 64 + nf * 8 + (lane & 3) * 2 + j]
                                    + (float)acc[mf][nf][h * 2 + j] * INV676;
                            bl = fminf(bl, s);
                            if (s < thr) {
                                int grow = row0 + myrow[ls];
                                int slot = atomicAdd(&g_ccnt[grow], 1);
                                if (slot < CAP)
                                    g_cand[grow * CAP + slot] =
                                        it * 256 + wn * 64 + nf * 8 + (lane & 3) * 2 + j;
                            }
                        }
                    if (it > 0) atomicMin(&rowbest[myrow[ls]], encf(bl));
                }
        }
        __syncthreads();
    }
}

// ============================================================================
// Exact fp32 rescoring of candidates (1 warp per row); full scan fallback.
// ============================================================================
__global__ __launch_bounds__(256) void vq_exact_cand(const float* __restrict__ z_e,
                                                     const float* __restrict__ cb) {
    const int lane = threadIdx.x & 31;
    const int wid  = (blockIdx.x * 256 + threadIdx.x) >> 5;
    const int nwarps = (gridDim.x * 256) >> 5;
    int nclamp = g_nclamp;
    bool clamp_bad = (nclamp > CLCAP);
    if (nclamp > CLCAP) nclamp = CLCAP;

    for (int row = wid; row < BROWS; row += nwarps) {
        float4 z0 = reinterpret_cast<const float4*>(z_e + (size_t)row * DDIM)[lane * 2];
        float4 z1 = reinterpret_cast<const float4*>(z_e + (size_t)row * DDIM)[lane * 2 + 1];
        float bv = 3.4e38f;
        int   bi = 0x7fffffff;

        auto eval = [&](int k) {
            const float4* e4 = reinterpret_cast<const float4*>(cb + (size_t)k * DDIM);
            float4 e0 = e4[lane * 2], e1 = e4[lane * 2 + 1];
            float d = z0.x * e0.x + z0.y * e0.y + z0.z * e0.z + z0.w * e0.w
                    + z1.x * e1.x + z1.y * e1.y + z1.z * e1.z + z1.w * e1.w;
#pragma unroll
            for (int o = 16; o; o >>= 1) d += __shfl_xor_sync(0xffffffffu, d, o);
            float s = g_esq[k] - d;
            if (s < bv || (s == bv && k < bi)) { bv = s; bi = k; }
        };

        int cnt = g_ccnt[row];
        if (cnt <= CAP && !clamp_bad) {
            for (int i = 0; i < cnt; i++) eval(g_cand[row * CAP + i]);
            for (int j = 0; j < nclamp; j++) eval(g_clampidx[j]);
        } else {
            for (int k = 0; k < KROWS; k++) eval(k);
        }
        if (lane == 0) g_row_idx[row] = bi;
    }
}

// ============================================================================
// Output epilogue (float4 lanes) + parallel final loss
// ============================================================================
__global__ __launch_bounds__(256)
void out_kernel(const float* __restrict__ z_e, const float* __restrict__ cb,
                float* __restrict__ out, long long out_size) {
    __shared__ float red[256];
    const int tid = threadIdx.x;
    const int row0 = blockIdx.x * 64;
    const int rsub = tid >> 6;
    const int c4   = tid & 63;
    float lsum = 0.f;
#pragma unroll 4
    for (int r = rsub; r < 64; r += 4) {
        const int row = row0 + r;
        const int idx = g_row_idx[row];
        float4 ze = reinterpret_cast<const float4*>(z_e + (size_t)row * DDIM)[c4];
        float4 zq = reinterpret_cast<const float4*>(cb + (size_t)idx * DDIM)[c4];
        float4 d;
        d.x = zq.x - ze.x; d.y = zq.y - ze.y; d.z = zq.z - ze.z; d.w = zq.w - ze.w;
        float4 o;
        o.x = ze.x + d.x; o.y = ze.y + d.y; o.z = ze.z + d.z; o.w = ze.w + d.w;
        long long pos = (long long)row * DDIM + c4 * 4;
        if (pos + 3 < out_size)
            reinterpret_cast<float4*>(out)[pos >> 2] = o;
        lsum += d.x * d.x + d.y * d.y + d.z * d.z + d.w * d.w;
    }
    if (tid < 64) {
        long long pos = (long long)BROWS * DDIM + row0 + tid;
        if (pos < out_size) out[pos] = (float)g_row_idx[row0 + tid];
    }
    red[tid] = lsum;
    __syncthreads();
#pragma unroll
    for (int st = 128; st > 0; st >>= 1) {
        if (tid < st) red[tid] += red[tid + st];
        __syncthreads();
    }
    if (tid == 0) g_partial[blockIdx.x] = red[0];
}

__global__ __launch_bounds__(512) void final_kernel(float* __restrict__ out,
                                                    long long out_size) {
    __shared__ float red[512];
    const int tid = threadIdx.x;
    red[tid] = g_partial[tid];
    __syncthreads();
#pragma unroll
    for (int st = 256; st > 0; st >>= 1) {
        if (tid < st) red[tid] += red[tid + st];
        __syncthreads();
    }
    if (tid == 0) {
        float mse = red[0] / ((float)BROWS * (float)DDIM);
        long long pos = (long long)BROWS * DDIM + BROWS;
        if (pos < out_size) out[pos] = 1.25f * mse;
    }
}

// ============================================================================
extern "C" void kernel_launch(void* const* d_in, const int* in_sizes, int n_in,
                              void* d_out, int out_size) {
    const float* z_e = (const float*)d_in[0];
    const float* cb  = (const float*)d_in[1];
    float* out       = (float*)d_out;

    prep_kernel<<<KROWS / 8, 256>>>(cb);
    quant_z<<<(BROWS * DDIM / 4) / 256, 256>>>(z_e);
    quant_cb<<<(KROWS * DDIM / 4) / 256, 256>>>(cb);

    cudaFuncSetAttribute(vq_screen, cudaFuncAttributeMaxDynamicSharedMemorySize,
                         SCR_SMEM);
    vq_screen<<<BROWS / 64, 256, SCR_SMEM>>>();

    vq_exact_cand<<<256, 256>>>(z_e, cb);
    out_kernel<<<BROWS / 64, 256>>>(z_e, cb, out, (long long)out_size);
    final_kernel<<<1, 512>>>(out, (long long)out_size);
}